// round 2
// baseline (speedup 1.0000x reference)
#include <cuda_runtime.h>
#include <cuda_bf16.h>

#define NN 50000
#define NE 800000

// ---------------- device scratch (static, allocation-free) ----------------
__device__ __align__(16) float g_h [(size_t)NN * 128]; // [n][v][{h0,h1x,h1y,h1z}]
__device__ __align__(16) float g_sc[(size_t)NN * 160]; // [n][ sc_s(32) | sc_g(32) | sc_v(96: w*3+m) ]
__device__ __align__(16) float g_s [(size_t)NN * 256]; // [n][u][8] = {t0a,t0b,t1a0,t1a1, t1a2,t1b0,t1b1,t1b2}

__device__ __forceinline__ float silu_f(float x) {
    return __fdividef(x, 1.0f + __expf(-x));
}

__device__ __forceinline__ void red_add_v4(float* p, float a, float b, float c, float d) {
    asm volatile("red.global.add.v4.f32 [%0], {%1,%2,%3,%4};"
                 :: "l"(p), "f"(a), "f"(b), "f"(c), "f"(d) : "memory");
}

// ================= kernel 1: per-node pre (self-connection + lin1) =================
// dynamic shared floats: WS[16384] WG[16384] WV[16384] L10[1024] L11[1024] X[16*256]
#define K1_WS  0
#define K1_WG  16384
#define K1_WV  32768
#define K1_L10 49152
#define K1_L11 50176
#define K1_X   51200
#define K1_FLOATS (K1_X + 16 * 256)
#define K1_BYTES  (K1_FLOATS * 4)

__global__ void __launch_bounds__(512) k_node_pre(
    const float* __restrict__ nf,  const float* __restrict__ attr,
    const float* __restrict__ w10, const float* __restrict__ w11,
    const float* __restrict__ ws,  const float* __restrict__ wg,
    const float* __restrict__ wv)
{
    extern __shared__ float sh[];
    const float SCN = 0.044194173824159216f; // 1/sqrt(512)
    const float L1  = 0.17677669529663687f;  // 1/sqrt(32)
    int tid = threadIdx.x;

    {
        const float4* p4 = (const float4*)ws;
        for (int i = tid; i < 4096; i += 512) {
            float4 v = __ldg(p4 + i);
            v.x *= SCN; v.y *= SCN; v.z *= SCN; v.w *= SCN;
            ((float4*)(sh + K1_WS))[i] = v;
        }
        p4 = (const float4*)wg;
        for (int i = tid; i < 4096; i += 512) {
            float4 v = __ldg(p4 + i);
            v.x *= SCN; v.y *= SCN; v.z *= SCN; v.w *= SCN;
            ((float4*)(sh + K1_WG))[i] = v;
        }
        p4 = (const float4*)wv;
        for (int i = tid; i < 4096; i += 512) {
            float4 v = __ldg(p4 + i);
            v.x *= SCN; v.y *= SCN; v.z *= SCN; v.w *= SCN;
            ((float4*)(sh + K1_WV))[i] = v;
        }
        p4 = (const float4*)w10;
        for (int i = tid; i < 256; i += 512) {
            float4 v = __ldg(p4 + i);
            v.x *= L1; v.y *= L1; v.z *= L1; v.w *= L1;
            ((float4*)(sh + K1_L10))[i] = v;
        }
        p4 = (const float4*)w11;
        for (int i = tid; i < 256; i += 512) {
            float4 v = __ldg(p4 + i);
            v.x *= L1; v.y *= L1; v.z *= L1; v.w *= L1;
            ((float4*)(sh + K1_L11))[i] = v;
        }
    }
    __syncthreads();

    int warp = tid >> 5, lane = tid & 31;
    float* shx = sh + K1_X + warp * 256;

    for (int p = blockIdx.x * 16 + warp; p < NN / 2; p += gridDim.x * 16) {
        int n0 = 2 * p, n1 = n0 + 1;
        ((float4*)shx)[lane]      = __ldg((const float4*)nf + (size_t)n0 * 32 + lane);
        ((float4*)shx)[32 + lane] = __ldg((const float4*)nf + (size_t)n1 * 32 + lane);
        __syncwarp();

        float z0[16], z1[16];
        {
            const float4* zp = (const float4*)attr + (size_t)n0 * 4;
            float4 t;
            t = __ldg(zp + 0); z0[0]  = t.x; z0[1]  = t.y; z0[2]  = t.z; z0[3]  = t.w;
            t = __ldg(zp + 1); z0[4]  = t.x; z0[5]  = t.y; z0[6]  = t.z; z0[7]  = t.w;
            t = __ldg(zp + 2); z0[8]  = t.x; z0[9]  = t.y; z0[10] = t.z; z0[11] = t.w;
            t = __ldg(zp + 3); z0[12] = t.x; z0[13] = t.y; z0[14] = t.z; z0[15] = t.w;
            zp = (const float4*)attr + (size_t)n1 * 4;
            t = __ldg(zp + 0); z1[0]  = t.x; z1[1]  = t.y; z1[2]  = t.z; z1[3]  = t.w;
            t = __ldg(zp + 1); z1[4]  = t.x; z1[5]  = t.y; z1[6]  = t.z; z1[7]  = t.w;
            t = __ldg(zp + 2); z1[8]  = t.x; z1[9]  = t.y; z1[10] = t.z; z1[11] = t.w;
            t = __ldg(zp + 3); z1[12] = t.x; z1[13] = t.y; z1[14] = t.z; z1[15] = t.w;
        }

        float as0 = 0.f, as1 = 0.f, ag0 = 0.f, ag1 = 0.f;
        float av0x = 0.f, av0y = 0.f, av0z = 0.f;
        float av1x = 0.f, av1y = 0.f, av1z = 0.f;
        float h00 = 0.f, h01 = 0.f;
        float h10x = 0.f, h10y = 0.f, h10z = 0.f;
        float h11x = 0.f, h11y = 0.f, h11z = 0.f;

        #pragma unroll 1
        for (int u = 0; u < 32; u++) {
            float x00 = shx[u],            x01 = shx[128 + u];
            float xa0 = shx[32 + u * 3],   xa1 = shx[33 + u * 3],  xa2 = shx[34 + u * 3];
            float xb0 = shx[160 + u * 3],  xb1 = shx[161 + u * 3], xb2 = shx[162 + u * 3];
            const float* wsp = sh + u * 512 + lane;
            float tsA = 0.f, tsB = 0.f, tgA = 0.f, tgB = 0.f, tvA = 0.f, tvB = 0.f;
            #pragma unroll
            for (int v = 0; v < 16; v++) {
                float a = wsp[K1_WS + v * 32];
                float b = wsp[K1_WG + v * 32];
                float c = wsp[K1_WV + v * 32];
                tsA += z0[v] * a; tsB += z1[v] * a;
                tgA += z0[v] * b; tgB += z1[v] * b;
                tvA += z0[v] * c; tvB += z1[v] * c;
            }
            as0 += x00 * tsA; as1 += x01 * tsB;
            ag0 += x00 * tgA; ag1 += x01 * tgB;
            av0x += xa0 * tvA; av0y += xa1 * tvA; av0z += xa2 * tvA;
            av1x += xb0 * tvB; av1y += xb1 * tvB; av1z += xb2 * tvB;
            float l10v = sh[K1_L10 + u * 32 + lane];
            h00 += x00 * l10v; h01 += x01 * l10v;
            float l11v = sh[K1_L11 + u * 32 + lane];
            h10x += xa0 * l11v; h10y += xa1 * l11v; h10z += xa2 * l11v;
            h11x += xb0 * l11v; h11y += xb1 * l11v; h11z += xb2 * l11v;
        }

        float* sc0 = g_sc + (size_t)n0 * 160;
        float* sc1 = g_sc + (size_t)n1 * 160;
        sc0[lane] = as0;            sc1[lane] = as1;
        sc0[32 + lane] = ag0;       sc1[32 + lane] = ag1;
        sc0[64 + lane * 3]     = av0x;  sc1[64 + lane * 3]     = av1x;
        sc0[64 + lane * 3 + 1] = av0y;  sc1[64 + lane * 3 + 1] = av1y;
        sc0[64 + lane * 3 + 2] = av0z;  sc1[64 + lane * 3 + 2] = av1z;

        float4 hv0 = make_float4(h00, h10x, h10y, h10z);
        float4 hv1 = make_float4(h01, h11x, h11y, h11z);
        ((float4*)g_h)[(size_t)n0 * 32 + lane] = hv0;
        ((float4*)g_h)[(size_t)n1 * 32 + lane] = hv1;
        __syncwarp();
    }
}

// ================= kernel 2: per-edge MLP + tensor-product messages + scatter =================
// dynamic shared floats: W0s[512] W1s[4096] W2p[8192]
#define KE_W0  0
#define KE_W1  512
#define KE_W2  4608
#define KE_FLOATS (KE_W2 + 8192)
#define KE_BYTES  (KE_FLOATS * 4)

__global__ void __launch_bounds__(384) k_edge(
    const float* __restrict__ esh, const float* __restrict__ emb,
    const float* __restrict__ fw0, const float* __restrict__ fw1,
    const float* __restrict__ fw2,
    const int* __restrict__ esrc, const int* __restrict__ edst)
{
    extern __shared__ float sh[];
    float* w0s = sh + KE_W0;
    float* w1s = sh + KE_W1;
    float* w2p = sh + KE_W2;
    int tid = threadIdx.x;
    const float S0 = 0.3535533905932738f; // 1/sqrt(8)
    const float S1 = 0.125f;              // 1/sqrt(64)
    const float S2 = 0.125f;

    for (int i = tid; i < 512; i += 384)  w0s[i] = __ldg(fw0 + i) * S0;
    for (int i = tid; i < 4096; i += 384) w1s[i] = __ldg(fw1 + i) * S1;
    for (int i = tid; i < 2048; i += 384) {
        int u = i >> 6, k = i & 63;
        const float* p = fw2 + k * 128 + u;
        float4 v = make_float4(__ldg(p) * S2, __ldg(p + 32) * S2,
                               __ldg(p + 64) * S2, __ldg(p + 96) * S2);
        ((float4*)w2p)[i] = v; // [u][k] float4
    }
    __syncthreads();

    int e = blockIdx.x * 384 + tid;
    if (e >= NE) return;

    float eb[8];
    {
        float4 b01 = __ldg((const float4*)emb + (size_t)e * 2);
        float4 b23 = __ldg((const float4*)emb + (size_t)e * 2 + 1);
        eb[0] = b01.x; eb[1] = b01.y; eb[2] = b01.z; eb[3] = b01.w;
        eb[4] = b23.x; eb[5] = b23.y; eb[6] = b23.z; eb[7] = b23.w;
    }

    // ---- layer 1: 8 -> 64 ----
    float a1[64];
    #pragma unroll
    for (int k = 0; k < 64; k++) a1[k] = 0.f;
    const float4* w0s4 = (const float4*)w0s;
    #pragma unroll
    for (int j = 0; j < 8; j++) {
        float b = eb[j];
        #pragma unroll
        for (int k4 = 0; k4 < 16; k4++) {
            float4 w = w0s4[j * 16 + k4];
            a1[4 * k4 + 0] += b * w.x;
            a1[4 * k4 + 1] += b * w.y;
            a1[4 * k4 + 2] += b * w.z;
            a1[4 * k4 + 3] += b * w.w;
        }
    }
    #pragma unroll
    for (int k = 0; k < 64; k++) a1[k] = silu_f(a1[k]);

    // ---- layer 2: 64 -> 64 ----
    float a2[64];
    #pragma unroll
    for (int k = 0; k < 64; k++) a2[k] = 0.f;
    const float4* w1s4 = (const float4*)w1s;
    #pragma unroll
    for (int j = 0; j < 64; j++) {
        float b = a1[j];
        #pragma unroll
        for (int k4 = 0; k4 < 16; k4++) {
            float4 w = w1s4[j * 16 + k4];
            a2[4 * k4 + 0] += b * w.x;
            a2[4 * k4 + 1] += b * w.y;
            a2[4 * k4 + 2] += b * w.z;
            a2[4 * k4 + 3] += b * w.w;
        }
    }
    #pragma unroll
    for (int k = 0; k < 64; k++) a2[k] = silu_f(a2[k]);

    // ---- layer 3 fused with message formation + scatter ----
    int s = __ldg(esrc + e);
    int d = __ldg(edst + e);
    float4 y = __ldg((const float4*)esh + e); // y0 = y.x, y1 = (y.y, y.z, y.w)
    const float4* gh4 = (const float4*)g_h + (size_t)s * 32;
    float* out_base = g_s + (size_t)d * 256;
    const float4* w2p4 = (const float4*)w2p;

    #pragma unroll 1
    for (int u = 0; u < 32; u++) {
        float m0 = 0.f, m1 = 0.f, m2 = 0.f, m3 = 0.f;
        #pragma unroll
        for (int k = 0; k < 64; k++) {
            float4 w = w2p4[u * 64 + k];
            m0 += a2[k] * w.x;
            m1 += a2[k] * w.y;
            m2 += a2[k] * w.z;
            m3 += a2[k] * w.w;
        }
        float4 ev = __ldg(gh4 + u); // {h0, h1x, h1y, h1z}
        float t0a = m0 * ev.x * y.x;
        float dd  = ev.y * y.y + ev.z * y.z + ev.w * y.w;
        float t0b = m3 * dd * 0.5773502691896258f; // 1/sqrt(3)
        float c1  = m1 * ev.x;
        float c2  = m2 * y.x;
        float* p = out_base + u * 8;
        red_add_v4(p,     t0a,      t0b,      c1 * y.y, c1 * y.z);
        red_add_v4(p + 4, c1 * y.w, c2 * ev.y, c2 * ev.z, c2 * ev.w);
    }
}

// ================= kernel 3: per-node post (lin2 + gate + output) =================
__global__ void __launch_bounds__(512) k_node_post(
    float* __restrict__ out,
    const float* __restrict__ w20, const float* __restrict__ w21)
{
    __shared__ float w20p[4096]; // [U][lane][2] = {w20[U][lane], w20[U][lane+32]}
    __shared__ float w21s[2048]; // [U][lane]
    __shared__ float ss[16 * 256];
    const float SC = 0.0078125f; // (1/sqrt(64)) * (1/16)
    int tid = threadIdx.x;

    for (int i = tid; i < 4096; i += 512) {
        int U = i >> 6, r = i & 63, ln = r >> 1, h = r & 1;
        w20p[i] = __ldg(w20 + U * 64 + h * 32 + ln) * SC;
    }
    for (int i = tid; i < 2048; i += 512) w21s[i] = __ldg(w21 + i) * SC;
    __syncthreads();

    int warp = tid >> 5, lane = tid & 31;
    float* srow = ss + warp * 256;

    for (int n = blockIdx.x * 16 + warp; n < NN; n += gridDim.x * 16) {
        const float4* sp = (const float4*)(g_s + (size_t)n * 256);
        ((float4*)srow)[lane]      = sp[lane];
        ((float4*)srow)[32 + lane] = sp[32 + lane];
        __syncwarp();

        float o0a = 0.f, o0b = 0.f, o1x = 0.f, o1y = 0.f, o1z = 0.f;
        #pragma unroll 4
        for (int u = 0; u < 32; u++) { // U = u  (t0a / t1a half)
            float s0v = srow[u * 8];
            float sx  = srow[u * 8 + 2], sy = srow[u * 8 + 3], sz = srow[u * 8 + 4];
            float2 wp = *(const float2*)&w20p[u * 64 + 2 * lane];
            float w1v = w21s[u * 32 + lane];
            o0a += s0v * wp.x; o0b += s0v * wp.y;
            o1x += sx * w1v;   o1y += sy * w1v;   o1z += sz * w1v;
        }
        #pragma unroll 4
        for (int u = 0; u < 32; u++) { // U = 32+u (t0b / t1b half)
            float s0v = srow[u * 8 + 1];
            float sx  = srow[u * 8 + 5], sy = srow[u * 8 + 6], sz = srow[u * 8 + 7];
            float2 wp = *(const float2*)&w20p[(u + 32) * 64 + 2 * lane];
            float w1v = w21s[(u + 32) * 32 + lane];
            o0a += s0v * wp.x; o0b += s0v * wp.y;
            o1x += sx * w1v;   o1y += sy * w1v;   o1z += sz * w1v;
        }

        const float* scb = g_sc + (size_t)n * 160;
        float scal = o0a + scb[lane];
        float gate = o0b + scb[32 + lane];
        float vx = o1x + scb[64 + lane * 3];
        float vy = o1y + scb[64 + lane * 3 + 1];
        float vz = o1z + scb[64 + lane * 3 + 2];
        float sg = silu_f(gate);
        float* op = out + (size_t)n * 128;
        op[lane] = silu_f(scal);
        op[32 + lane * 3]     = sg * vx;
        op[33 + lane * 3]     = sg * vy;
        op[34 + lane * 3]     = sg * vz;
        __syncwarp();
    }
}

// ================= launch =================
extern "C" void kernel_launch(void* const* d_in, const int* in_sizes, int n_in,
                              void* d_out, int out_size) {
    const float* nf   = (const float*)d_in[0];
    const float* attr = (const float*)d_in[1];
    const float* esh  = (const float*)d_in[2];
    const float* emb  = (const float*)d_in[3];
    const float* w10  = (const float*)d_in[4];
    const float* w11  = (const float*)d_in[5];
    const float* fw0  = (const float*)d_in[6];
    const float* fw1  = (const float*)d_in[7];
    const float* fw2  = (const float*)d_in[8];
    const float* ws   = (const float*)d_in[9];
    const float* wg   = (const float*)d_in[10];
    const float* wv   = (const float*)d_in[11];
    const float* w20  = (const float*)d_in[12];
    const float* w21  = (const float*)d_in[13];
    const int* esrc   = (const int*)d_in[14];
    const int* edst   = (const int*)d_in[15];
    float* out = (float*)d_out;

    void* gs_addr = nullptr;
    cudaGetSymbolAddress(&gs_addr, g_s);
    cudaMemsetAsync(gs_addr, 0, (size_t)NN * 256 * sizeof(float), 0);

    cudaFuncSetAttribute(k_node_pre, cudaFuncAttributeMaxDynamicSharedMemorySize, K1_BYTES);
    cudaFuncSetAttribute(k_edge, cudaFuncAttributeMaxDynamicSharedMemorySize, KE_BYTES);

    k_node_pre<<<148, 512, K1_BYTES>>>(nf, attr, w10, w11, ws, wg, wv);
    k_edge<<<(NE + 383) / 384, 384, KE_BYTES>>>(esh, emb, fw0, fw1, fw2, esrc, edst);
    k_node_post<<<592, 512>>>(out, w20, w21);
}

// round 4
// speedup vs baseline: 1.0049x; 1.0049x over previous
#include <cuda_runtime.h>
#include <cuda_bf16.h>

#define NN 50000
#define NE 800000

// ---------------- device scratch (static, allocation-free) ----------------
__device__ __align__(16) float g_h [(size_t)NN * 128]; // [n][v][{h0,h1x,h1y,h1z}]
__device__ __align__(16) float g_sc[(size_t)NN * 160]; // [n][ sc_s(32) | sc_g(32) | sc_v(96: w*3+m) ]
__device__ __align__(16) float g_s [(size_t)NN * 256]; // [n][u][8] = {t0a,t0b,t1a0,t1a1, t1a2,t1b0,t1b1,t1b2}

__device__ __forceinline__ float silu_f(float x) {
    return __fdividef(x, 1.0f + __expf(-x));
}

__device__ __forceinline__ void red_add_v4(float* p, float a, float b, float c, float d) {
    asm volatile("red.global.add.v4.f32 [%0], {%1,%2,%3,%4};"
                 :: "l"(p), "f"(a), "f"(b), "f"(c), "f"(d) : "memory");
}

// ---- packed f32x2 helpers (Blackwell FFMA2 pipe) ----
typedef unsigned long long ull;

__device__ __forceinline__ ull pk2(float x, float y) {
    ull r; asm("mov.b64 %0, {%1,%2};" : "=l"(r) : "f"(x), "f"(y)); return r;
}
__device__ __forceinline__ void upk2(ull v, float& x, float& y) {
    asm("mov.b64 {%0,%1}, %2;" : "=f"(x), "=f"(y) : "l"(v));
}
__device__ __forceinline__ ull fma2(ull a, ull b, ull c) {
    ull d; asm("fma.rn.f32x2 %0, %1, %2, %3;" : "=l"(d) : "l"(a), "l"(b), "l"(c)); return d;
}

// ================= kernel 1: per-node pre (self-connection + lin1) =================
// dynamic shared floats: WS[16384] WG[16384] WV[16384] L10[1024] L11[1024] X[16*256]
#define K1_WS  0
#define K1_WG  16384
#define K1_WV  32768
#define K1_L10 49152
#define K1_L11 50176
#define K1_X   51200
#define K1_FLOATS (K1_X + 16 * 256)
#define K1_BYTES  (K1_FLOATS * 4)

__global__ void __launch_bounds__(512) k_node_pre(
    const float* __restrict__ nf,  const float* __restrict__ attr,
    const float* __restrict__ w10, const float* __restrict__ w11,
    const float* __restrict__ ws,  const float* __restrict__ wg,
    const float* __restrict__ wv)
{
    extern __shared__ float sh[];
    const float SCN = 0.044194173824159216f; // 1/sqrt(512)
    const float L1  = 0.17677669529663687f;  // 1/sqrt(32)
    int tid = threadIdx.x;

    {
        const float4* p4 = (const float4*)ws;
        for (int i = tid; i < 4096; i += 512) {
            float4 v = __ldg(p4 + i);
            v.x *= SCN; v.y *= SCN; v.z *= SCN; v.w *= SCN;
            ((float4*)(sh + K1_WS))[i] = v;
        }
        p4 = (const float4*)wg;
        for (int i = tid; i < 4096; i += 512) {
            float4 v = __ldg(p4 + i);
            v.x *= SCN; v.y *= SCN; v.z *= SCN; v.w *= SCN;
            ((float4*)(sh + K1_WG))[i] = v;
        }
        p4 = (const float4*)wv;
        for (int i = tid; i < 4096; i += 512) {
            float4 v = __ldg(p4 + i);
            v.x *= SCN; v.y *= SCN; v.z *= SCN; v.w *= SCN;
            ((float4*)(sh + K1_WV))[i] = v;
        }
        p4 = (const float4*)w10;
        for (int i = tid; i < 256; i += 512) {
            float4 v = __ldg(p4 + i);
            v.x *= L1; v.y *= L1; v.z *= L1; v.w *= L1;
            ((float4*)(sh + K1_L10))[i] = v;
        }
        p4 = (const float4*)w11;
        for (int i = tid; i < 256; i += 512) {
            float4 v = __ldg(p4 + i);
            v.x *= L1; v.y *= L1; v.z *= L1; v.w *= L1;
            ((float4*)(sh + K1_L11))[i] = v;
        }
    }
    __syncthreads();

    int warp = tid >> 5, lane = tid & 31;
    float* shx = sh + K1_X + warp * 256;

    for (int p = blockIdx.x * 16 + warp; p < NN / 2; p += gridDim.x * 16) {
        int n0 = 2 * p, n1 = n0 + 1;
        ((float4*)shx)[lane]      = __ldg((const float4*)nf + (size_t)n0 * 32 + lane);
        ((float4*)shx)[32 + lane] = __ldg((const float4*)nf + (size_t)n1 * 32 + lane);
        __syncwarp();

        float z0[16], z1[16];
        {
            const float4* zp = (const float4*)attr + (size_t)n0 * 4;
            float4 t;
            t = __ldg(zp + 0); z0[0]  = t.x; z0[1]  = t.y; z0[2]  = t.z; z0[3]  = t.w;
            t = __ldg(zp + 1); z0[4]  = t.x; z0[5]  = t.y; z0[6]  = t.z; z0[7]  = t.w;
            t = __ldg(zp + 2); z0[8]  = t.x; z0[9]  = t.y; z0[10] = t.z; z0[11] = t.w;
            t = __ldg(zp + 3); z0[12] = t.x; z0[13] = t.y; z0[14] = t.z; z0[15] = t.w;
            zp = (const float4*)attr + (size_t)n1 * 4;
            t = __ldg(zp + 0); z1[0]  = t.x; z1[1]  = t.y; z1[2]  = t.z; z1[3]  = t.w;
            t = __ldg(zp + 1); z1[4]  = t.x; z1[5]  = t.y; z1[6]  = t.z; z1[7]  = t.w;
            t = __ldg(zp + 2); z1[8]  = t.x; z1[9]  = t.y; z1[10] = t.z; z1[11] = t.w;
            t = __ldg(zp + 3); z1[12] = t.x; z1[13] = t.y; z1[14] = t.z; z1[15] = t.w;
        }

        float as0 = 0.f, as1 = 0.f, ag0 = 0.f, ag1 = 0.f;
        float av0x = 0.f, av0y = 0.f, av0z = 0.f;
        float av1x = 0.f, av1y = 0.f, av1z = 0.f;
        float h00 = 0.f, h01 = 0.f;
        float h10x = 0.f, h10y = 0.f, h10z = 0.f;
        float h11x = 0.f, h11y = 0.f, h11z = 0.f;

        #pragma unroll 1
        for (int u = 0; u < 32; u++) {
            float x00 = shx[u],            x01 = shx[128 + u];
            float xa0 = shx[32 + u * 3],   xa1 = shx[33 + u * 3],  xa2 = shx[34 + u * 3];
            float xb0 = shx[160 + u * 3],  xb1 = shx[161 + u * 3], xb2 = shx[162 + u * 3];
            const float* wsp = sh + u * 512 + lane;
            float tsA = 0.f, tsB = 0.f, tgA = 0.f, tgB = 0.f, tvA = 0.f, tvB = 0.f;
            #pragma unroll
            for (int v = 0; v < 16; v++) {
                float a = wsp[K1_WS + v * 32];
                float b = wsp[K1_WG + v * 32];
                float c = wsp[K1_WV + v * 32];
                tsA += z0[v] * a; tsB += z1[v] * a;
                tgA += z0[v] * b; tgB += z1[v] * b;
                tvA += z0[v] * c; tvB += z1[v] * c;
            }
            as0 += x00 * tsA; as1 += x01 * tsB;
            ag0 += x00 * tgA; ag1 += x01 * tgB;
            av0x += xa0 * tvA; av0y += xa1 * tvA; av0z += xa2 * tvA;
            av1x += xb0 * tvB; av1y += xb1 * tvB; av1z += xb2 * tvB;
            float l10v = sh[K1_L10 + u * 32 + lane];
            h00 += x00 * l10v; h01 += x01 * l10v;
            float l11v = sh[K1_L11 + u * 32 + lane];
            h10x += xa0 * l11v; h10y += xa1 * l11v; h10z += xa2 * l11v;
            h11x += xb0 * l11v; h11y += xb1 * l11v; h11z += xb2 * l11v;
        }

        float* sc0 = g_sc + (size_t)n0 * 160;
        float* sc1 = g_sc + (size_t)n1 * 160;
        sc0[lane] = as0;            sc1[lane] = as1;
        sc0[32 + lane] = ag0;       sc1[32 + lane] = ag1;
        sc0[64 + lane * 3]     = av0x;  sc1[64 + lane * 3]     = av1x;
        sc0[64 + lane * 3 + 1] = av0y;  sc1[64 + lane * 3 + 1] = av1y;
        sc0[64 + lane * 3 + 2] = av0z;  sc1[64 + lane * 3 + 2] = av1z;

        float4 hv0 = make_float4(h00, h10x, h10y, h10z);
        float4 hv1 = make_float4(h01, h11x, h11y, h11z);
        ((float4*)g_h)[(size_t)n0 * 32 + lane] = hv0;
        ((float4*)g_h)[(size_t)n1 * 32 + lane] = hv1;
        __syncwarp();
    }
}

// ================= kernel 2: per-edge MLP (f32x2 packed) + messages + scatter =================
// dynamic shared floats: W0[512] W1[4096] W2q[8192]
// W2q layout: [u][t(=k/2)][8] = {w0e,w0o, w1e,w1o, w2e,w2o, w3e,w3o}
#define KE_W0  0
#define KE_W1  512
#define KE_W2  4608
#define KE_FLOATS (KE_W2 + 8192)
#define KE_BYTES  (KE_FLOATS * 4)

__global__ void __launch_bounds__(384) k_edge(
    const float* __restrict__ esh, const float* __restrict__ emb,
    const float* __restrict__ fw0, const float* __restrict__ fw1,
    const float* __restrict__ fw2,
    const int* __restrict__ esrc, const int* __restrict__ edst)
{
    extern __shared__ float sh[];
    float* w0s = sh + KE_W0;
    float* w1s = sh + KE_W1;
    float* w2q = sh + KE_W2;
    int tid = threadIdx.x;
    const float S0 = 0.3535533905932738f; // 1/sqrt(8)
    const float S1 = 0.125f;              // 1/sqrt(64)
    const float S2 = 0.125f;

    for (int i = tid; i < 512; i += 384)  w0s[i] = __ldg(fw0 + i) * S0;
    for (int i = tid; i < 4096; i += 384) w1s[i] = __ldg(fw1 + i) * S1;
    for (int i = tid; i < 8192; i += 384) {
        int u = i >> 8, r = i & 255, t = r >> 3, c = r & 7;
        int k = 2 * t + (c & 1);
        int col = (c >> 1) * 32 + u;
        w2q[i] = __ldg(fw2 + k * 128 + col) * S2;
    }
    __syncthreads();

    int e = blockIdx.x * 384 + tid;
    if (e >= NE) return;

    float eb[8];
    {
        float4 b01 = __ldg((const float4*)emb + (size_t)e * 2);
        float4 b23 = __ldg((const float4*)emb + (size_t)e * 2 + 1);
        eb[0] = b01.x; eb[1] = b01.y; eb[2] = b01.z; eb[3] = b01.w;
        eb[4] = b23.x; eb[5] = b23.y; eb[6] = b23.z; eb[7] = b23.w;
    }

    // ---- layer 1: 8 -> 64, packed over k-pairs ----
    ull acc[32];
    #pragma unroll
    for (int t = 0; t < 32; t++) acc[t] = 0ULL;
    {
        const ulonglong2* w0q = (const ulonglong2*)w0s;
        #pragma unroll
        for (int j = 0; j < 8; j++) {
            ull bd = pk2(eb[j], eb[j]);
            #pragma unroll
            for (int q = 0; q < 16; q++) {
                ulonglong2 w = w0q[j * 16 + q];
                acc[2 * q]     = fma2(bd, w.x, acc[2 * q]);
                acc[2 * q + 1] = fma2(bd, w.y, acc[2 * q + 1]);
            }
        }
    }
    float a1[64];
    #pragma unroll
    for (int t = 0; t < 32; t++) {
        float x, y; upk2(acc[t], x, y);
        a1[2 * t] = silu_f(x); a1[2 * t + 1] = silu_f(y);
    }

    // ---- layer 2: 64 -> 64, packed over k-pairs ----
    #pragma unroll
    for (int t = 0; t < 32; t++) acc[t] = 0ULL;
    {
        const ulonglong2* w1q = (const ulonglong2*)w1s;
        #pragma unroll 8
        for (int j = 0; j < 64; j++) {
            ull bd = pk2(a1[j], a1[j]);
            #pragma unroll
            for (int q = 0; q < 16; q++) {
                ulonglong2 w = w1q[j * 16 + q];
                acc[2 * q]     = fma2(bd, w.x, acc[2 * q]);
                acc[2 * q + 1] = fma2(bd, w.y, acc[2 * q + 1]);
            }
        }
    }
    // silu and KEEP packed as k-pairs for layer 3
    ull a2p[32];
    #pragma unroll
    for (int t = 0; t < 32; t++) {
        float x, y; upk2(acc[t], x, y);
        a2p[t] = pk2(silu_f(x), silu_f(y));
    }

    // ---- layer 3 fused with message formation + scatter ----
    int s = __ldg(esrc + e);
    int d = __ldg(edst + e);
    float4 y4 = __ldg((const float4*)esh + e); // y0 = y4.x, y1 = (y4.y, y4.z, y4.w)
    const float4* gh4 = (const float4*)g_h + (size_t)s * 32;
    float* out_base = g_s + (size_t)d * 256;
    const ulonglong2* w2q2 = (const ulonglong2*)w2q; // 2 per (u,t)

    #pragma unroll 1
    for (int u = 0; u < 32; u++) {
        ull p0 = 0ULL, p1 = 0ULL, p2 = 0ULL, p3 = 0ULL;
        const ulonglong2* wp = w2q2 + (size_t)u * 64;
        #pragma unroll
        for (int t = 0; t < 32; t++) {
            ulonglong2 wa = wp[2 * t];
            ulonglong2 wb = wp[2 * t + 1];
            p0 = fma2(a2p[t], wa.x, p0);
            p1 = fma2(a2p[t], wa.y, p1);
            p2 = fma2(a2p[t], wb.x, p2);
            p3 = fma2(a2p[t], wb.y, p3);
        }
        float m0, m1, m2, m3, lo, hi;
        upk2(p0, lo, hi); m0 = lo + hi;
        upk2(p1, lo, hi); m1 = lo + hi;
        upk2(p2, lo, hi); m2 = lo + hi;
        upk2(p3, lo, hi); m3 = lo + hi;

        float4 ev = __ldg(gh4 + u); // {h0, h1x, h1y, h1z}
        float t0a = m0 * ev.x * y4.x;
        float dd  = ev.y * y4.y + ev.z * y4.z + ev.w * y4.w;
        float t0b = m3 * dd * 0.5773502691896258f; // 1/sqrt(3)
        float c1  = m1 * ev.x;
        float c2  = m2 * y4.x;
        float* p = out_base + u * 8;
        red_add_v4(p,     t0a,       t0b,       c1 * y4.y, c1 * y4.z);
        red_add_v4(p + 4, c1 * y4.w, c2 * ev.y, c2 * ev.z,  c2 * ev.w);
    }
}

// ================= kernel 3: per-node post (lin2 + gate + output) =================
__global__ void __launch_bounds__(512) k_node_post(
    float* __restrict__ out,
    const float* __restrict__ w20, const float* __restrict__ w21)
{
    __shared__ float w20p[4096]; // [U][lane][2] = {w20[U][lane], w20[U][lane+32]}
    __shared__ float w21s[2048]; // [U][lane]
    __shared__ float ss[16 * 256];
    const float SC = 0.0078125f; // (1/sqrt(64)) * (1/16)
    int tid = threadIdx.x;

    for (int i = tid; i < 4096; i += 512) {
        int U = i >> 6, r = i & 63, ln = r >> 1, h = r & 1;
        w20p[i] = __ldg(w20 + U * 64 + h * 32 + ln) * SC;
    }
    for (int i = tid; i < 2048; i += 512) w21s[i] = __ldg(w21 + i) * SC;
    __syncthreads();

    int warp = tid >> 5, lane = tid & 31;
    float* srow = ss + warp * 256;

    for (int n = blockIdx.x * 16 + warp; n < NN; n += gridDim.x * 16) {
        const float4* sp = (const float4*)(g_s + (size_t)n * 256);
        ((float4*)srow)[lane]      = sp[lane];
        ((float4*)srow)[32 + lane] = sp[32 + lane];
        __syncwarp();

        float o0a = 0.f, o0b = 0.f, o1x = 0.f, o1y = 0.f, o1z = 0.f;
        #pragma unroll 4
        for (int u = 0; u < 32; u++) { // U = u  (t0a / t1a half)
            float s0v = srow[u * 8];
            float sx  = srow[u * 8 + 2], sy = srow[u * 8 + 3], sz = srow[u * 8 + 4];
            float2 wp = *(const float2*)&w20p[u * 64 + 2 * lane];
            float w1v = w21s[u * 32 + lane];
            o0a += s0v * wp.x; o0b += s0v * wp.y;
            o1x += sx * w1v;   o1y += sy * w1v;   o1z += sz * w1v;
        }
        #pragma unroll 4
        for (int u = 0; u < 32; u++) { // U = 32+u (t0b / t1b half)
            float s0v = srow[u * 8 + 1];
            float sx  = srow[u * 8 + 5], sy = srow[u * 8 + 6], sz = srow[u * 8 + 7];
            float2 wp = *(const float2*)&w20p[(u + 32) * 64 + 2 * lane];
            float w1v = w21s[(u + 32) * 32 + lane];
            o0a += s0v * wp.x; o0b += s0v * wp.y;
            o1x += sx * w1v;   o1y += sy * w1v;   o1z += sz * w1v;
        }

        const float* scb = g_sc + (size_t)n * 160;
        float scal = o0a + scb[lane];
        float gate = o0b + scb[32 + lane];
        float vx = o1x + scb[64 + lane * 3];
        float vy = o1y + scb[64 + lane * 3 + 1];
        float vz = o1z + scb[64 + lane * 3 + 2];
        float sg = silu_f(gate);
        float* op = out + (size_t)n * 128;
        op[lane] = silu_f(scal);
        op[32 + lane * 3]     = sg * vx;
        op[33 + lane * 3]     = sg * vy;
        op[34 + lane * 3]     = sg * vz;
        __syncwarp();
    }
}

// ================= launch =================
extern "C" void kernel_launch(void* const* d_in, const int* in_sizes, int n_in,
                              void* d_out, int out_size) {
    const float* nf   = (const float*)d_in[0];
    const float* attr = (const float*)d_in[1];
    const float* esh  = (const float*)d_in[2];
    const float* emb  = (const float*)d_in[3];
    const float* w10  = (const float*)d_in[4];
    const float* w11  = (const float*)d_in[5];
    const float* fw0  = (const float*)d_in[6];
    const float* fw1  = (const float*)d_in[7];
    const float* fw2  = (const float*)d_in[8];
    const float* ws   = (const float*)d_in[9];
    const float* wg   = (const float*)d_in[10];
    const float* wv   = (const float*)d_in[11];
    const float* w20  = (const float*)d_in[12];
    const float* w21  = (const float*)d_in[13];
    const int* esrc   = (const int*)d_in[14];
    const int* edst   = (const int*)d_in[15];
    float* out = (float*)d_out;

    void* gs_addr = nullptr;
    cudaGetSymbolAddress(&gs_addr, g_s);
    cudaMemsetAsync(gs_addr, 0, (size_t)NN * 256 * sizeof(float), 0);

    cudaFuncSetAttribute(k_node_pre, cudaFuncAttributeMaxDynamicSharedMemorySize, K1_BYTES);
    cudaFuncSetAttribute(k_edge, cudaFuncAttributeMaxDynamicSharedMemorySize, KE_BYTES);

    k_node_pre<<<148, 512, K1_BYTES>>>(nf, attr, w10, w11, ws, wg, wv);
    k_edge<<<(NE + 383) / 384, 384, KE_BYTES>>>(esh, emb, fw0, fw1, fw2, esrc, edst);
    k_node_post<<<592, 512>>>(out, w20, w21);
}